// round 6
// baseline (speedup 1.0000x reference)
#include <cuda_runtime.h>
#include <cuda_fp16.h>

#define Bz 32
#define Cc 384
#define Nn 4096
#define Mm 64
#define TN 128
#define NT 4                    // n-tiles per CTA
#define NGRP 8                  // CTAs per batch
#define WST 392                 // Ws row stride (halfs), 784B = 49*16
#define XSTH 136                // xh row stride (halfs), 272B = 17*16 (ldmatrix conflict-free)
#define SSTH 136                // Sh row stride (halfs)
#define LST 132                 // Ls row stride (floats)

// smem layout (bytes)
#define OFF_WS    0
#define OFF_XH    (OFF_WS + Mm * WST * 2)        // 50176
#define OFF_LS    (OFF_XH + Cc * XSTH * 2)       // 154624
#define OFF_SH    (OFF_LS + Mm * LST * 4)        // 188416
#define OFF_BIAS  (OFF_SH + Mm * SSTH * 2)       // 205824
#define OFF_CINV  (OFF_BIAS + 64 * 4)            // 206080
#define OFF_SCR   (OFF_CINV + 128 * 4)           // 206592
#define SMEM_BYTES (OFF_SCR + 256 * 4)           // 207616

__device__ __half g_Wh[Mm * Cc];                     // f16(U @ Vw)
__device__ float  g_b[Mm];                           // U @ Vb
__device__ float  g_part[(size_t)Bz * NGRP * Cc * Mm];  // per-CTA T partials (25 MB)

__global__ void precompute_kernel(const float* __restrict__ Vw,
                                  const float* __restrict__ Vb,
                                  const float* __restrict__ U) {
    int t = blockIdx.x * blockDim.x + threadIdx.x;
    if (t < Mm * Cc) {
        int m = t / Cc, c = t % Cc;
        float s = 0.f;
        #pragma unroll
        for (int r = 0; r < 16; ++r) s += U[m * 16 + r] * Vw[r * Cc + c];
        g_Wh[t] = __float2half_rn(s);
    }
    if (t < Mm) {
        float s = 0.f;
        #pragma unroll
        for (int r = 0; r < 16; ++r) s += U[t * 16 + r] * Vb[r];
        g_b[t] = s;
    }
}

__global__ void reduceT_kernel(float4* __restrict__ outT4) {
    const int Q = Cc * Mm / 4;                      // 6144 float4 per partial
    int i = blockIdx.x * blockDim.x + threadIdx.x;  // over Bz*Q
    int b = i / Q, r = i % Q;
    const float4* p = (const float4*)g_part + (size_t)b * NGRP * Q + r;
    float4 s = make_float4(0.f, 0.f, 0.f, 0.f);
    #pragma unroll
    for (int k = 0; k < NGRP; ++k) {
        float4 v = p[(size_t)k * Q];
        s.x += v.x; s.y += v.y; s.z += v.z; s.w += v.w;
    }
    outT4[i] = s;
}

__device__ __forceinline__ void ldsm_x4(unsigned r[4], unsigned saddr) {
    asm volatile("ldmatrix.sync.aligned.m8n8.x4.shared.b16 {%0,%1,%2,%3}, [%4];"
                 : "=r"(r[0]), "=r"(r[1]), "=r"(r[2]), "=r"(r[3]) : "r"(saddr));
}
__device__ __forceinline__ void ldsm_x2t(unsigned& r0, unsigned& r1, unsigned saddr) {
    asm volatile("ldmatrix.sync.aligned.m8n8.x2.trans.shared.b16 {%0,%1}, [%2];"
                 : "=r"(r0), "=r"(r1) : "r"(saddr));
}
__device__ __forceinline__ void ldsm_x2(unsigned& r0, unsigned& r1, unsigned saddr) {
    asm volatile("ldmatrix.sync.aligned.m8n8.x2.shared.b16 {%0,%1}, [%2];"
                 : "=r"(r0), "=r"(r1) : "r"(saddr));
}
__device__ __forceinline__ void mma_f16(float c[4], const unsigned a[4],
                                        unsigned b0, unsigned b1) {
    asm volatile(
        "mma.sync.aligned.m16n8k16.row.col.f32.f16.f16.f32 "
        "{%0,%1,%2,%3}, {%4,%5,%6,%7}, {%8,%9}, {%0,%1,%2,%3};"
        : "+f"(c[0]), "+f"(c[1]), "+f"(c[2]), "+f"(c[3])
        : "r"(a[0]), "r"(a[1]), "r"(a[2]), "r"(a[3]), "r"(b0), "r"(b1));
}

__global__ __launch_bounds__(256, 1)
void main_kernel(const float* __restrict__ x,
                 float* __restrict__ outS) {
    extern __shared__ char smem[];
    __half* Ws    = (__half*)(smem + OFF_WS);
    __half* xh    = (__half*)(smem + OFF_XH);
    float*  Ls    = (float*)(smem + OFF_LS);
    __half* Sh    = (__half*)(smem + OFF_SH);
    float*  bias  = (float*)(smem + OFF_BIAS);
    float*  cinv  = (float*)(smem + OFF_CINV);
    float*  scr   = (float*)(smem + OFF_SCR);

    const unsigned xh_a = (unsigned)__cvta_generic_to_shared(xh);
    const unsigned sh_a = (unsigned)__cvta_generic_to_shared(Sh);
    const unsigned ws_a = (unsigned)__cvta_generic_to_shared(Ws);

    const int tid  = threadIdx.x;
    const int warp = tid >> 5;
    const int lane = tid & 31;
    const int g    = lane >> 2;
    const int t4   = lane & 3;

    const int b    = blockIdx.x >> 3;
    const int tIdx = blockIdx.x & 7;
    const float* xb = x + (size_t)b * Cc * Nn;

    // per-lane ldmatrix offsets
    const int wrow  = (lane & 7) + ((lane >> 3) & 1) * 8;
    const int wcolh = (lane >> 4) * 8;
    const unsigned ws_lane = ws_a + (unsigned)(wrow * WST + wcolh) * 2;
    const unsigned xb_lane = xh_a + (unsigned)((lane & 15) * XSTH) * 2;      // GEMM1 B (trans)
    const unsigned xa_lane = xh_a + (unsigned)(wrow * XSTH + wcolh) * 2;     // GEMM2 A
    const unsigned sh_lane = sh_a + (unsigned)((lane & 7) * SSTH + ((lane >> 3) & 1) * 8) * 2;

    // warp-local x stripe coords: warp w owns columns [16w, 16w+16)
    const int cw   = warp * 16;
    const int rsub = lane >> 2;        // 0..7
    const int cq   = (lane & 3) * 4;   // 0,4,8,12

    // ---- stage W (f16) and bias ----
    {
        const uint4* src = (const uint4*)g_Wh;     // 3072 uint4, 48 per row
        #pragma unroll
        for (int i = 0; i < 12; ++i) {
            int u = tid + i * 256;
            int row = u / 48, c16 = u % 48;
            *(uint4*)(Ws + row * WST + c16 * 8) = src[u];
        }
        if (tid < Mm) bias[tid] = g_b[tid];
    }

    const int nw = warp * 16;
    float acc2[3][8][4];
    #pragma unroll
    for (int i = 0; i < 3; ++i)
        #pragma unroll
        for (int j = 0; j < 8; ++j)
            #pragma unroll
            for (int k = 0; k < 4; ++k) acc2[i][j][k] = 0.f;

    for (int it = 0; it < NT; ++it) {
        const int n0 = (tIdx * NT + it) * TN;
        __syncthreads();   // xh/Sh reuse guard vs previous tile's GEMM2

        // per-warp stripe base in gmem: rows x cols [cw, cw+16)
        const float* xs = xb + n0 + cw + cq;

        float acc1[4][2][4];
        #pragma unroll
        for (int i = 0; i < 4; ++i)
            #pragma unroll
            for (int j = 0; j < 2; ++j)
                #pragma unroll
                for (int k = 0; k < 4; ++k) acc1[i][j][k] = 0.f;

        // prefetch chunk 0 (rows 0..31 of this warp's stripe)
        float4 pre[4];
        #pragma unroll
        for (int p = 0; p < 4; ++p)
            pre[p] = *(const float4*)(xs + (size_t)(rsub + p * 8) * Nn);

        for (int ck = 0; ck < 12; ++ck) {
            float4 nxt[4];
            if (ck < 11) {
                const float* src = xs + (size_t)((ck + 1) * 32) * Nn;
                #pragma unroll
                for (int p = 0; p < 4; ++p)
                    nxt[p] = *(const float4*)(src + (size_t)(rsub + p * 8) * Nn);
            }
            // convert + store current chunk into this warp's xh columns
            #pragma unroll
            for (int p = 0; p < 4; ++p) {
                __half2 h0 = __floats2half2_rn(pre[p].x, pre[p].y);
                __half2 h1 = __floats2half2_rn(pre[p].z, pre[p].w);
                *(uint2*)(xh + (ck * 32 + rsub + p * 8) * XSTH + cw + cq) =
                    make_uint2(*(unsigned*)&h0, *(unsigned*)&h1);
            }
            __syncwarp();

            // GEMM1 on these 32 k-rows (2 k16 steps) — warp-local data only
            #pragma unroll
            for (int ks = 0; ks < 2; ++ks) {
                const int k0 = ck * 32 + ks * 16;
                unsigned bf0[2], bf1[2];
                ldsm_x2t(bf0[0], bf0[1], xb_lane + (unsigned)(k0 * XSTH + nw) * 2);
                ldsm_x2t(bf1[0], bf1[1], xb_lane + (unsigned)(k0 * XSTH + nw + 8) * 2);
                #pragma unroll
                for (int mt = 0; mt < 4; ++mt) {
                    unsigned a[4];
                    ldsm_x4(a, ws_lane + (unsigned)(mt * 16 * WST + k0) * 2);
                    mma_f16(acc1[mt][0], a, bf0[0], bf0[1]);
                    mma_f16(acc1[mt][1], a, bf1[0], bf1[1]);
                }
            }
            #pragma unroll
            for (int p = 0; p < 4; ++p) pre[p] = nxt[p];
        }

        // store L (+bias) to smem
        #pragma unroll
        for (int mt = 0; mt < 4; ++mt)
            #pragma unroll
            for (int nt = 0; nt < 2; ++nt) {
                int row = mt * 16 + g;
                int col = nw + nt * 8 + t4 * 2;
                float b0 = bias[row], b1 = bias[row + 8];
                *(float2*)(Ls + row * LST + col) =
                    make_float2(acc1[mt][nt][0] + b0, acc1[mt][nt][1] + b0);
                *(float2*)(Ls + (row + 8) * LST + col) =
                    make_float2(acc1[mt][nt][2] + b1, acc1[mt][nt][3] + b1);
            }
        __syncthreads();   // publishes xh (all warps) + Ls

        // ---- softmax over 64 tokens per column, all 256 threads ----
        {
            const int j = tid & 127, h = tid >> 7;
            const int m0 = h * 32;
            float mx = -1e30f;
            #pragma unroll 8
            for (int m = m0; m < m0 + 32; ++m)
                mx = fmaxf(mx, Ls[m * LST + j]);
            scr[h * 128 + j] = mx;
            __syncthreads();
            mx = fmaxf(scr[j], scr[128 + j]);
            __syncthreads();
            float s = 0.f;
            #pragma unroll 8
            for (int m = m0; m < m0 + 32; ++m) {
                float e = __expf(Ls[m * LST + j] - mx);
                Ls[m * LST + j] = e;
                s += e;
            }
            scr[h * 128 + j] = s;
            __syncthreads();
            if (h == 0) cinv[j] = __frcp_rn(scr[j] + scr[128 + j]);
        }
        __syncthreads();

        // ---- write S (f32) + build f16 copy ----
        {
            float* Sb = outS + (size_t)b * Mm * Nn + n0;
            #pragma unroll
            for (int i = 0; i < 8; ++i) {
                int u = tid + i * 256;
                int m = u >> 5, c4 = u & 31;
                float4 v = *(const float4*)(Ls + m * LST + c4 * 4);
                float4 w = *(const float4*)(cinv + c4 * 4);
                v.x *= w.x; v.y *= w.y; v.z *= w.z; v.w *= w.w;
                *(float4*)(Sb + (size_t)m * Nn + c4 * 4) = v;
                __half2 h0 = __floats2half2_rn(v.x, v.y);
                __half2 h1 = __floats2half2_rn(v.z, v.w);
                *(uint2*)(Sh + m * SSTH + c4 * 4) =
                    make_uint2(*(unsigned*)&h0, *(unsigned*)&h1);
            }
        }
        __syncthreads();

        // ---- GEMM2: T partial += x_tile @ S_tile^T ----
        for (int k0 = 0; k0 < TN; k0 += 16) {
            unsigned bfr[8][2];
            #pragma unroll
            for (int nt = 0; nt < 8; ++nt)
                ldsm_x2(bfr[nt][0], bfr[nt][1],
                        sh_lane + (unsigned)(nt * 8 * SSTH + k0) * 2);
            #pragma unroll
            for (int cbi = 0; cbi < 3; ++cbi) {
                unsigned a[4];
                ldsm_x4(a, xa_lane + (unsigned)((cbi * 128 + warp * 16) * XSTH + k0) * 2);
                #pragma unroll
                for (int nt = 0; nt < 8; ++nt)
                    mma_f16(acc2[cbi][nt], a, bfr[nt][0], bfr[nt][1]);
            }
        }
    }

    // ---- write T partials (plain STG) ----
    {
        float* Pb = g_part + (size_t)(b * NGRP + tIdx) * (Cc * Mm);
        #pragma unroll
        for (int cbi = 0; cbi < 3; ++cbi)
            #pragma unroll
            for (int nt = 0; nt < 8; ++nt) {
                int row = cbi * 128 + warp * 16 + g;
                int col = nt * 8 + t4 * 2;
                *(float2*)(Pb + row * Mm + col) =
                    make_float2(acc2[cbi][nt][0], acc2[cbi][nt][1]);
                *(float2*)(Pb + (row + 8) * Mm + col) =
                    make_float2(acc2[cbi][nt][2], acc2[cbi][nt][3]);
            }
    }
}

extern "C" void kernel_launch(void* const* d_in, const int* in_sizes, int n_in,
                              void* d_out, int out_size) {
    const float* x  = (const float*)d_in[0];
    const float* Vw = (const float*)d_in[1];
    const float* Vb = (const float*)d_in[2];
    const float* U  = (const float*)d_in[3];

    float* out  = (float*)d_out;
    float* outT = out;                          // [B, C, M]
    float* outS = out + (size_t)Bz * Cc * Mm;   // [B, M, N]

    cudaFuncSetAttribute(main_kernel, cudaFuncAttributeMaxDynamicSharedMemorySize, SMEM_BYTES);

    precompute_kernel<<<(Mm * Cc + 255) / 256, 256>>>(Vw, Vb, U);
    main_kernel<<<Bz * NGRP, 256, SMEM_BYTES>>>(x, outS);
    reduceT_kernel<<<(Bz * Cc * Mm / 4) / 256, 256>>>((float4*)outT);
}